// round 2
// baseline (speedup 1.0000x reference)
#include <cuda_runtime.h>

#define B_    8
#define F_IN  32
#define CN    256
#define M_    64
#define C_OUT 64
#define C_CAT 224   // (2*3+1)*32
#define KC    16
#define XS_STRIDE 36
#define WS_STRIDE 68

// Scratch: H[b][m][fc][c], fc in [0,224): piece p at fc=32p.
// pieces: 0=x^T, 1=x1_b0, 2=x2_b0, 3=x1_b1, 4=x2_b1, 5=x1_b2, 6=x2_b2
__device__ float g_H[(size_t)B_ * M_ * C_CAT * CN];

// ---------------- cp.async helpers ----------------
__device__ __forceinline__ void cp_async16(void* s, const void* g) {
    unsigned sa = (unsigned)__cvta_generic_to_shared(s);
    asm volatile("cp.async.cg.shared.global [%0], [%1], 16;\n" :: "r"(sa), "l"(g));
}
__device__ __forceinline__ void cp_commit() {
    asm volatile("cp.async.commit_group;\n");
}
template<int N> __device__ __forceinline__ void cp_wait() {
    asm volatile("cp.async.wait_group %0;\n" :: "n"(N));
}

// ---------------- Kernel 1: x[b,f,n,m] -> H[b][m][0..31][n] ----------------
__global__ __launch_bounds__(256) void k_transpose(const float* __restrict__ x) {
    int id = blockIdx.x;           // ((b*32 + f)*8 + nt)
    int nt = id & 7;
    int f  = (id >> 3) & 31;
    int b  = id >> 8;

    __shared__ float ts[32][65];
    int t  = threadIdx.x;
    int m  = t & 63;
    int nl = t >> 6;               // 0..3
    const float* xp = x + ((size_t)(b * F_IN + f) * CN + nt * 32) * M_;
#pragma unroll
    for (int i = 0; i < 8; ++i) {
        int r = nl + 4 * i;
        ts[r][m] = xp[(size_t)r * M_ + m];
    }
    __syncthreads();
    int nl2 = t & 31;
    int mg  = t >> 5;              // 0..7
#pragma unroll
    for (int i = 0; i < 8; ++i) {
        int mm = mg + 8 * i;
        g_H[((size_t)(b * M_ + mm) * C_CAT + f) * CN + nt * 32 + nl2] = ts[nl2][mm];
    }
}

// ---------------- fused nconv hop ----------------
// out[f][v] = sum_n xin[n][f] * A[n][v]   (32 x 256 = [32x256k] @ [256k x 256v])
__device__ __forceinline__ void hop(const float* __restrict__ Ag,  // A[b][m]: 256x256
                                    const float* __restrict__ xin, // smem [256][XS_STRIDE]
                                    float* __restrict__ As,        // smem 2*KC*256
                                    float acc[8][4],
                                    int fg, int vh, int tv)
{
#pragma unroll
    for (int i = 0; i < 8; ++i)
#pragma unroll
        for (int j = 0; j < 4; ++j) acc[i][j] = 0.0f;

    int t  = threadIdx.x;
    int lr = t >> 6;               // 0..3
    int lc = (t & 63) * 4;         // float4 column

    // prefetch chunk 0 into buffer 0
#pragma unroll
    for (int r = 0; r < 4; ++r)
        cp_async16(&As[(lr + 4 * r) * CN + lc], Ag + (size_t)(lr + 4 * r) * CN + lc);
    cp_commit();

    for (int ch = 0; ch < CN / KC; ++ch) {
        float* buf = As + (ch & 1) * (KC * CN);
        if (ch < CN / KC - 1) {
            float* nbuf = As + ((ch + 1) & 1) * (KC * CN);
            const float* Agc = Ag + (size_t)(ch + 1) * KC * CN;
#pragma unroll
            for (int r = 0; r < 4; ++r)
                cp_async16(&nbuf[(lr + 4 * r) * CN + lc], Agc + (size_t)(lr + 4 * r) * CN + lc);
            cp_commit();
            cp_wait<1>();
        } else {
            cp_wait<0>();
        }
        __syncthreads();
#pragma unroll
        for (int kk = 0; kk < KC; ++kk) {
            int n = ch * KC + kk;
            float4 x0 = *(const float4*)&xin[n * XS_STRIDE + 8 * fg];
            float4 x1 = *(const float4*)&xin[n * XS_STRIDE + 8 * fg + 4];
            float4 a  = *(const float4*)&buf[kk * CN + 128 * vh + 4 * tv];
            float xv[8] = {x0.x, x0.y, x0.z, x0.w, x1.x, x1.y, x1.z, x1.w};
            float av[4] = {a.x, a.y, a.z, a.w};
#pragma unroll
            for (int i = 0; i < 8; ++i)
#pragma unroll
                for (int j = 0; j < 4; ++j)
                    acc[i][j] = fmaf(xv[i], av[j], acc[i][j]);
        }
        __syncthreads();
    }
}

// ---------------- Kernel 2: fused double-hop nconv ----------------
// block = (base kb, b, m); computes x1 = x@A and x2 = x1@A, writes pieces.
__global__ __launch_bounds__(256, 2) void k_nconv(const float* __restrict__ b0,
                                                  const float* __restrict__ b1,
                                                  const float* __restrict__ b2)
{
    extern __shared__ float smem[];
    float* xs  = smem;                      // 256*36
    float* x1s = smem + 256 * XS_STRIDE;    // 256*36
    float* As  = x1s + 256 * XS_STRIDE;     // 2*KC*256

    int id = blockIdx.x;                    // 0..1535
    int kb = id >> 9;
    int bm = id & 511;
    const float* Ag = (kb == 0 ? b0 : (kb == 1 ? b1 : b2)) + (size_t)bm * (CN * CN);
    float* Hbm = g_H + (size_t)bm * (C_CAT * CN);

    int t  = threadIdx.x;
    int tv = t & 31;
    int tg = t >> 5;
    int fg = tg & 3;
    int vh = tg >> 2;

    // fill xs[n][f] from piece 0 (n = t)
    {
        const float* p0 = Hbm;
#pragma unroll
        for (int f = 0; f < 32; ++f)
            xs[t * XS_STRIDE + f] = p0[f * CN + t];
    }
    __syncthreads();

    float acc[8][4];

    // hop 1: x1 = x @ A
    hop(Ag, xs, As, acc, fg, vh, tv);
    {
        float* Hp = Hbm + (size_t)(32 * (1 + 2 * kb)) * CN;
#pragma unroll
        for (int j = 0; j < 4; ++j) {
            int v = 128 * vh + 4 * tv + j;
            float4 w0 = make_float4(acc[0][j], acc[1][j], acc[2][j], acc[3][j]);
            float4 w1 = make_float4(acc[4][j], acc[5][j], acc[6][j], acc[7][j]);
            *(float4*)&x1s[v * XS_STRIDE + 8 * fg]     = w0;
            *(float4*)&x1s[v * XS_STRIDE + 8 * fg + 4] = w1;
        }
#pragma unroll
        for (int i = 0; i < 8; ++i) {
            float4 w = make_float4(acc[i][0], acc[i][1], acc[i][2], acc[i][3]);
            *(float4*)&Hp[(8 * fg + i) * CN + 128 * vh + 4 * tv] = w;
        }
    }
    __syncthreads();

    // hop 2: x2 = x1 @ A  (A re-read, hits L2)
    hop(Ag, x1s, As, acc, fg, vh, tv);
    {
        float* Hp = Hbm + (size_t)(32 * (2 + 2 * kb)) * CN;
#pragma unroll
        for (int i = 0; i < 8; ++i) {
            float4 w = make_float4(acc[i][0], acc[i][1], acc[i][2], acc[i][3]);
            *(float4*)&Hp[(8 * fg + i) * CN + 128 * vh + 4 * tv] = w;
        }
    }
}

// ---------------- Kernel 3: y[b,o,c,m] = W[o,:] . H[b][m][:][c] + bias[o] ----------------
__global__ __launch_bounds__(256, 2) void k_final(const float* __restrict__ W,
                                                  const float* __restrict__ bias,
                                                  float* __restrict__ y)
{
    extern __shared__ float smem[];
    float* Ws = smem;                       // 224*68 transposed W: Ws[fc][o]
    float* Hs = Ws + C_CAT * WS_STRIDE;     // 2*KC*256

    int bm = blockIdx.x;
    int b  = bm >> 6;
    int m  = bm & 63;
    const float* Hbm = g_H + (size_t)bm * (C_CAT * CN);

    int t  = threadIdx.x;
    int tv = t & 31;
    int og = t >> 5;                        // 0..7

    int lr = t >> 6;
    int lc = (t & 63) * 4;

    // prefetch H chunk 0
#pragma unroll
    for (int r = 0; r < 4; ++r)
        cp_async16(&Hs[(lr + 4 * r) * CN + lc], Hbm + (size_t)(lr + 4 * r) * CN + lc);
    cp_commit();

    // fill Ws[fc][o]
    for (int i = t; i < C_OUT * C_CAT; i += 256) {
        int o = i / C_CAT, fc = i % C_CAT;
        Ws[fc * WS_STRIDE + o] = W[i];
    }
    float bv[8];
#pragma unroll
    for (int i = 0; i < 8; ++i) bv[i] = bias[8 * og + i];

    float acc[8][2][4];
#pragma unroll
    for (int i = 0; i < 8; ++i)
#pragma unroll
        for (int q = 0; q < 2; ++q)
#pragma unroll
            for (int j = 0; j < 4; ++j) acc[i][q][j] = 0.0f;

    const int NCH = C_CAT / KC;  // 14
    for (int ch = 0; ch < NCH; ++ch) {
        float* buf = Hs + (ch & 1) * (KC * CN);
        if (ch < NCH - 1) {
            float* nbuf = Hs + ((ch + 1) & 1) * (KC * CN);
            const float* Hc = Hbm + (size_t)(ch + 1) * KC * CN;
#pragma unroll
            for (int r = 0; r < 4; ++r)
                cp_async16(&nbuf[(lr + 4 * r) * CN + lc], Hc + (size_t)(lr + 4 * r) * CN + lc);
            cp_commit();
            cp_wait<1>();
        } else {
            cp_wait<0>();
        }
        __syncthreads();
#pragma unroll
        for (int kk = 0; kk < KC; ++kk) {
            int k = ch * KC + kk;
            float4 w0 = *(const float4*)&Ws[k * WS_STRIDE + 8 * og];
            float4 w1 = *(const float4*)&Ws[k * WS_STRIDE + 8 * og + 4];
            float4 h0 = *(const float4*)&buf[kk * CN + 4 * tv];
            float4 h1 = *(const float4*)&buf[kk * CN + 128 + 4 * tv];
            float wv[8]   = {w0.x, w0.y, w0.z, w0.w, w1.x, w1.y, w1.z, w1.w};
            float hv[2][4] = {{h0.x, h0.y, h0.z, h0.w}, {h1.x, h1.y, h1.z, h1.w}};
#pragma unroll
            for (int i = 0; i < 8; ++i)
#pragma unroll
                for (int q = 0; q < 2; ++q)
#pragma unroll
                    for (int j = 0; j < 4; ++j)
                        acc[i][q][j] = fmaf(wv[i], hv[q][j], acc[i][q][j]);
        }
        __syncthreads();
    }

    // scattered stores: y[((b*64+o)*256+c)*64 + m]
#pragma unroll
    for (int i = 0; i < 8; ++i) {
        int o = 8 * og + i;
        float bb = bv[i];
        size_t ob = ((size_t)(b * C_OUT + o) * CN) * M_ + m;
#pragma unroll
        for (int q = 0; q < 2; ++q)
#pragma unroll
            for (int j = 0; j < 4; ++j) {
                int c = 128 * q + 4 * tv + j;
                y[ob + (size_t)c * M_] = acc[i][q][j] + bb;
            }
    }
}

// ---------------- launch ----------------
extern "C" void kernel_launch(void* const* d_in, const int* in_sizes, int n_in,
                              void* d_out, int out_size) {
    const float* x    = (const float*)d_in[0];
    const float* b0   = (const float*)d_in[1];
    const float* b1   = (const float*)d_in[2];
    const float* b2   = (const float*)d_in[3];
    const float* W    = (const float*)d_in[4];
    const float* bias = (const float*)d_in[5];
    float* y = (float*)d_out;

    const int SMEM_K2 = (2 * 256 * XS_STRIDE + 2 * KC * CN) * 4;   // 106,496 B
    const int SMEM_K3 = (C_CAT * WS_STRIDE + 2 * KC * CN) * 4;     //  93,696 B
    cudaFuncSetAttribute(k_nconv, cudaFuncAttributeMaxDynamicSharedMemorySize, SMEM_K2);
    cudaFuncSetAttribute(k_final, cudaFuncAttributeMaxDynamicSharedMemorySize, SMEM_K3);

    k_transpose<<<2048, 256>>>(x);
    k_nconv<<<1536, 256, SMEM_K2>>>(b0, b1, b2);
    k_final<<<512, 256, SMEM_K3>>>(W, bias, y);
}

// round 3
// speedup vs baseline: 1.0818x; 1.0818x over previous
#include <cuda_runtime.h>
#include <cstdint>

#define B_    8
#define F_IN  32
#define CN    256
#define M_    64
#define C_OUT 64
#define C_CAT 224   // (2*3+1)*32
#define KC    16
#define XS_STRIDE 36
#define WS_STRIDE 68

// Scratch: H[b][m][fc][c], fc in [0,224): piece p at fc=32p.
// pieces: 0=x^T, 1=x1_b0, 2=x2_b0, 3=x1_b1, 4=x2_b1, 5=x1_b2, 6=x2_b2
__device__ float g_H[(size_t)B_ * M_ * C_CAT * CN];

// ---------------- packed f32x2 helpers ----------------
__device__ __forceinline__ uint64_t pk2(float lo, float hi) {
    uint64_t r; asm("mov.b64 %0,{%1,%2};" : "=l"(r) : "f"(lo), "f"(hi)); return r;
}
__device__ __forceinline__ void upk2(uint64_t p, float& lo, float& hi) {
    asm("mov.b64 {%0,%1},%2;" : "=f"(lo), "=f"(hi) : "l"(p));
}
__device__ __forceinline__ void ffma2(uint64_t& d, uint64_t a, uint64_t b) {
    asm("fma.rn.f32x2 %0,%1,%2,%0;" : "+l"(d) : "l"(a), "l"(b));
}

// ---------------- cp.async helpers ----------------
__device__ __forceinline__ void cp_async16(void* s, const void* g) {
    unsigned sa = (unsigned)__cvta_generic_to_shared(s);
    asm volatile("cp.async.cg.shared.global [%0], [%1], 16;\n" :: "r"(sa), "l"(g));
}
__device__ __forceinline__ void cp_commit() {
    asm volatile("cp.async.commit_group;\n");
}
template<int N> __device__ __forceinline__ void cp_wait() {
    asm volatile("cp.async.wait_group %0;\n" :: "n"(N));
}

// ---------------- Kernel 1: x[b,f,n,m] -> H[b][m][0..31][n] ----------------
__global__ __launch_bounds__(256) void k_transpose(const float* __restrict__ x) {
    int id = blockIdx.x;           // ((b*32 + f)*8 + nt)
    int nt = id & 7;
    int f  = (id >> 3) & 31;
    int b  = id >> 8;

    __shared__ float ts[32][65];
    int t  = threadIdx.x;
    int m  = t & 63;
    int nl = t >> 6;               // 0..3
    const float* xp = x + ((size_t)(b * F_IN + f) * CN + nt * 32) * M_;
#pragma unroll
    for (int i = 0; i < 8; ++i) {
        int r = nl + 4 * i;
        ts[r][m] = xp[(size_t)r * M_ + m];
    }
    __syncthreads();
    int nl2 = t & 31;
    int mg  = t >> 5;              // 0..7
#pragma unroll
    for (int i = 0; i < 8; ++i) {
        int mm = mg + 8 * i;
        g_H[((size_t)(b * M_ + mm) * C_CAT + f) * CN + nt * 32 + nl2] = ts[nl2][mm];
    }
}

// ---------------- fused nconv hop (FFMA2 inner loop) ----------------
// out[f][v] = sum_n xin[n][f] * A[n][v]   (32 x 256 = [32x256k] @ [256k x 256v])
// acc2[p][j] packs f-pair (2p, 2p+1) for v-column j.
__device__ __forceinline__ void hop(const float* __restrict__ Ag,  // A[b][m]: 256x256
                                    const float* __restrict__ xin, // smem [256][XS_STRIDE]
                                    float* __restrict__ As,        // smem 2*KC*256
                                    uint64_t acc2[4][4],
                                    int fg, int vh, int tv)
{
#pragma unroll
    for (int p = 0; p < 4; ++p)
#pragma unroll
        for (int j = 0; j < 4; ++j) acc2[p][j] = 0ull;

    int t  = threadIdx.x;
    int lr = t >> 6;               // 0..3
    int lc = (t & 63) * 4;         // float4 column

    // prefetch chunk 0 into buffer 0
#pragma unroll
    for (int r = 0; r < 4; ++r)
        cp_async16(&As[(lr + 4 * r) * CN + lc], Ag + (size_t)(lr + 4 * r) * CN + lc);
    cp_commit();

    for (int ch = 0; ch < CN / KC; ++ch) {
        float* buf = As + (ch & 1) * (KC * CN);
        if (ch < CN / KC - 1) {
            float* nbuf = As + ((ch + 1) & 1) * (KC * CN);
            const float* Agc = Ag + (size_t)(ch + 1) * KC * CN;
#pragma unroll
            for (int r = 0; r < 4; ++r)
                cp_async16(&nbuf[(lr + 4 * r) * CN + lc], Agc + (size_t)(lr + 4 * r) * CN + lc);
            cp_commit();
            cp_wait<1>();
        } else {
            cp_wait<0>();
        }
        __syncthreads();
#pragma unroll
        for (int kk = 0; kk < KC; ++kk) {
            int n = ch * KC + kk;
            float4 x0 = *(const float4*)&xin[n * XS_STRIDE + 8 * fg];
            float4 x1 = *(const float4*)&xin[n * XS_STRIDE + 8 * fg + 4];
            float4 a  = *(const float4*)&buf[kk * CN + 128 * vh + 4 * tv];
            // f-pairs: already adjacent registers from the float4 loads
            uint64_t xp[4] = { pk2(x0.x, x0.y), pk2(x0.z, x0.w),
                               pk2(x1.x, x1.y), pk2(x1.z, x1.w) };
            // A values duplicated into both packed lanes
            uint64_t ad[4] = { pk2(a.x, a.x), pk2(a.y, a.y),
                               pk2(a.z, a.z), pk2(a.w, a.w) };
#pragma unroll
            for (int p = 0; p < 4; ++p)
#pragma unroll
                for (int j = 0; j < 4; ++j)
                    ffma2(acc2[p][j], xp[p], ad[j]);
        }
        __syncthreads();
    }
}

// ---------------- Kernel 2: fused double-hop nconv ----------------
// block = (base kb, b, m); computes x1 = x@A and x2 = x1@A, writes pieces.
__global__ __launch_bounds__(256, 2) void k_nconv(const float* __restrict__ b0,
                                                  const float* __restrict__ b1,
                                                  const float* __restrict__ b2)
{
    extern __shared__ float smem[];
    float* xs  = smem;                      // 256*36
    float* x1s = smem + 256 * XS_STRIDE;    // 256*36
    float* As  = x1s + 256 * XS_STRIDE;     // 2*KC*256

    int id = blockIdx.x;                    // 0..1535
    int kb = id >> 9;
    int bm = id & 511;
    const float* Ag = (kb == 0 ? b0 : (kb == 1 ? b1 : b2)) + (size_t)bm * (CN * CN);
    float* Hbm = g_H + (size_t)bm * (C_CAT * CN);

    int t  = threadIdx.x;
    int tv = t & 31;
    int tg = t >> 5;
    int fg = tg & 3;
    int vh = tg >> 2;

    // fill xs[n][f] from piece 0 (n = t)
    {
        const float* p0 = Hbm;
#pragma unroll
        for (int f = 0; f < 32; ++f)
            xs[t * XS_STRIDE + f] = p0[f * CN + t];
    }
    __syncthreads();

    uint64_t acc2[4][4];
    float accf[8][4];

    // hop 1: x1 = x @ A
    hop(Ag, xs, As, acc2, fg, vh, tv);
#pragma unroll
    for (int p = 0; p < 4; ++p)
#pragma unroll
        for (int j = 0; j < 4; ++j)
            upk2(acc2[p][j], accf[2 * p][j], accf[2 * p + 1][j]);
    {
        float* Hp = Hbm + (size_t)(32 * (1 + 2 * kb)) * CN;
#pragma unroll
        for (int j = 0; j < 4; ++j) {
            int v = 128 * vh + 4 * tv + j;
            float4 w0 = make_float4(accf[0][j], accf[1][j], accf[2][j], accf[3][j]);
            float4 w1 = make_float4(accf[4][j], accf[5][j], accf[6][j], accf[7][j]);
            *(float4*)&x1s[v * XS_STRIDE + 8 * fg]     = w0;
            *(float4*)&x1s[v * XS_STRIDE + 8 * fg + 4] = w1;
        }
#pragma unroll
        for (int i = 0; i < 8; ++i) {
            float4 w = make_float4(accf[i][0], accf[i][1], accf[i][2], accf[i][3]);
            *(float4*)&Hp[(8 * fg + i) * CN + 128 * vh + 4 * tv] = w;
        }
    }
    __syncthreads();

    // hop 2: x2 = x1 @ A  (A re-read, hits L2)
    hop(Ag, x1s, As, acc2, fg, vh, tv);
#pragma unroll
    for (int p = 0; p < 4; ++p)
#pragma unroll
        for (int j = 0; j < 4; ++j)
            upk2(acc2[p][j], accf[2 * p][j], accf[2 * p + 1][j]);
    {
        float* Hp = Hbm + (size_t)(32 * (2 + 2 * kb)) * CN;
#pragma unroll
        for (int i = 0; i < 8; ++i) {
            float4 w = make_float4(accf[i][0], accf[i][1], accf[i][2], accf[i][3]);
            *(float4*)&Hp[(8 * fg + i) * CN + 128 * vh + 4 * tv] = w;
        }
    }
}

// ---------------- Kernel 3: y[b,o,c,m] = W[o,:] . H[b][m][:][c] + bias[o] ----------------
__global__ __launch_bounds__(256, 2) void k_final(const float* __restrict__ W,
                                                  const float* __restrict__ bias,
                                                  float* __restrict__ y)
{
    extern __shared__ float smem[];
    float* Ws = smem;                       // 224*68 transposed W: Ws[fc][o]
    float* Hs = Ws + C_CAT * WS_STRIDE;     // 2*KC*256

    int bm = blockIdx.x;
    int b  = bm >> 6;
    int m  = bm & 63;
    const float* Hbm = g_H + (size_t)bm * (C_CAT * CN);

    int t  = threadIdx.x;
    int tv = t & 31;
    int og = t >> 5;                        // 0..7

    int lr = t >> 6;
    int lc = (t & 63) * 4;

    // prefetch H chunk 0
#pragma unroll
    for (int r = 0; r < 4; ++r)
        cp_async16(&Hs[(lr + 4 * r) * CN + lc], Hbm + (size_t)(lr + 4 * r) * CN + lc);
    cp_commit();

    // fill Ws[fc][o]
    for (int i = t; i < C_OUT * C_CAT; i += 256) {
        int o = i / C_CAT, fc = i % C_CAT;
        Ws[fc * WS_STRIDE + o] = W[i];
    }
    float bv[8];
#pragma unroll
    for (int i = 0; i < 8; ++i) bv[i] = bias[8 * og + i];

    // acc2[p][q][j]: o-pair (2p,2p+1) x c-half q x c-col j
    uint64_t acc2[4][2][4];
#pragma unroll
    for (int p = 0; p < 4; ++p)
#pragma unroll
        for (int q = 0; q < 2; ++q)
#pragma unroll
            for (int j = 0; j < 4; ++j) acc2[p][q][j] = 0ull;

    const int NCH = C_CAT / KC;  // 14
    for (int ch = 0; ch < NCH; ++ch) {
        float* buf = Hs + (ch & 1) * (KC * CN);
        if (ch < NCH - 1) {
            float* nbuf = Hs + ((ch + 1) & 1) * (KC * CN);
            const float* Hc = Hbm + (size_t)(ch + 1) * KC * CN;
#pragma unroll
            for (int r = 0; r < 4; ++r)
                cp_async16(&nbuf[(lr + 4 * r) * CN + lc], Hc + (size_t)(lr + 4 * r) * CN + lc);
            cp_commit();
            cp_wait<1>();
        } else {
            cp_wait<0>();
        }
        __syncthreads();
#pragma unroll
        for (int kk = 0; kk < KC; ++kk) {
            int k = ch * WS_STRIDE * 0 + ch * KC + kk; // k index
            float4 w0 = *(const float4*)&Ws[(ch * KC + kk) * WS_STRIDE + 8 * og];
            float4 w1 = *(const float4*)&Ws[(ch * KC + kk) * WS_STRIDE + 8 * og + 4];
            float4 h0 = *(const float4*)&buf[kk * CN + 4 * tv];
            float4 h1 = *(const float4*)&buf[kk * CN + 128 + 4 * tv];
            (void)k;
            uint64_t wp[4] = { pk2(w0.x, w0.y), pk2(w0.z, w0.w),
                               pk2(w1.x, w1.y), pk2(w1.z, w1.w) };
            uint64_t hd[2][4] = {
                { pk2(h0.x, h0.x), pk2(h0.y, h0.y), pk2(h0.z, h0.z), pk2(h0.w, h0.w) },
                { pk2(h1.x, h1.x), pk2(h1.y, h1.y), pk2(h1.z, h1.z), pk2(h1.w, h1.w) }
            };
#pragma unroll
            for (int p = 0; p < 4; ++p)
#pragma unroll
                for (int q = 0; q < 2; ++q)
#pragma unroll
                    for (int j = 0; j < 4; ++j)
                        ffma2(acc2[p][q][j], wp[p], hd[q][j]);
        }
        __syncthreads();
    }

    // unpack + scattered stores: y[((b*64+o)*256+c)*64 + m]
#pragma unroll
    for (int p = 0; p < 4; ++p) {
#pragma unroll
        for (int q = 0; q < 2; ++q)
#pragma unroll
            for (int j = 0; j < 4; ++j) {
                float lo, hi;
                upk2(acc2[p][q][j], lo, hi);
                int o0 = 8 * og + 2 * p;
                int c  = 128 * q + 4 * tv + j;
                size_t ob0 = ((size_t)(b * C_OUT + o0) * CN + c) * M_ + m;
                size_t ob1 = ((size_t)(b * C_OUT + o0 + 1) * CN + c) * M_ + m;
                y[ob0] = lo + bv[2 * p];
                y[ob1] = hi + bv[2 * p + 1];
            }
    }
}

// ---------------- launch ----------------
extern "C" void kernel_launch(void* const* d_in, const int* in_sizes, int n_in,
                              void* d_out, int out_size) {
    const float* x    = (const float*)d_in[0];
    const float* b0   = (const float*)d_in[1];
    const float* b1   = (const float*)d_in[2];
    const float* b2   = (const float*)d_in[3];
    const float* W    = (const float*)d_in[4];
    const float* bias = (const float*)d_in[5];
    float* y = (float*)d_out;

    const int SMEM_K2 = (2 * 256 * XS_STRIDE + 2 * KC * CN) * 4;   // 106,496 B
    const int SMEM_K3 = (C_CAT * WS_STRIDE + 2 * KC * CN) * 4;     //  93,696 B
    cudaFuncSetAttribute(k_nconv, cudaFuncAttributeMaxDynamicSharedMemorySize, SMEM_K2);
    cudaFuncSetAttribute(k_final, cudaFuncAttributeMaxDynamicSharedMemorySize, SMEM_K3);

    k_transpose<<<2048, 256>>>(x);
    k_nconv<<<1536, 256, SMEM_K2>>>(b0, b1, b2);
    k_final<<<512, 256, SMEM_K3>>>(W, bias, y);
}

// round 6
// speedup vs baseline: 1.3505x; 1.2484x over previous
#include <cuda_runtime.h>
#include <cstdint>

#define B_    8
#define F_IN  32
#define CN    256
#define M_    64
#define C_OUT 64
#define C_CAT 224   // (2*3+1)*32
#define KC    16
#define WS_STRIDE 68

// Scratch: H[b][m][fc][c], fc in [0,224): piece p at fc=32p.
// pieces: 0=x^T, 1=x1_b0, 2=x2_b0, 3=x1_b1, 4=x2_b1, 5=x1_b2, 6=x2_b2
__device__ float g_H[(size_t)B_ * M_ * C_CAT * CN];

// ================= shared helpers =================
__device__ __forceinline__ uint32_t smem_u32(const void* p) {
    uint32_t a;
    asm("{ .reg .u64 t; cvta.to.shared.u64 t, %1; cvt.u32.u64 %0, t; }" : "=r"(a) : "l"(p));
    return a;
}
__device__ __forceinline__ void cp_async16(uint32_t sa, const void* g) {
    asm volatile("cp.async.cg.shared.global [%0], [%1], 16;\n" :: "r"(sa), "l"(g));
}
__device__ __forceinline__ void cp_commit() { asm volatile("cp.async.commit_group;\n"); }
template<int N> __device__ __forceinline__ void cp_wait() {
    asm volatile("cp.async.wait_group %0;\n" :: "n"(N));
}

// packed f32x2 helpers (k_final)
__device__ __forceinline__ uint64_t pk2(float lo, float hi) {
    uint64_t r; asm("mov.b64 %0,{%1,%2};" : "=l"(r) : "f"(lo), "f"(hi)); return r;
}
__device__ __forceinline__ void upk2(uint64_t p, float& lo, float& hi) {
    asm("mov.b64 {%0,%1},%2;" : "=f"(lo), "=f"(hi) : "l"(p));
}
__device__ __forceinline__ void ffma2(uint64_t& d, uint64_t a, uint64_t b) {
    asm("fma.rn.f32x2 %0,%1,%2,%0;" : "+l"(d) : "l"(a), "l"(b));
}

// bf16 hi/lo split: (a0,a1) -> packed hi bf16x2 + packed residual bf16x2 (lane0 = a0)
__device__ __forceinline__ void split2(float a0, float a1, uint32_t& hi2, uint32_t& lo2) {
    asm("cvt.rn.bf16x2.f32 %0, %1, %2;" : "=r"(hi2) : "f"(a1), "f"(a0));
    float h0 = __uint_as_float(hi2 << 16);
    float h1 = __uint_as_float(hi2 & 0xFFFF0000u);
    float l0 = a0 - h0, l1 = a1 - h1;
    asm("cvt.rn.bf16x2.f32 %0, %1, %2;" : "=r"(lo2) : "f"(l1), "f"(l0));
}

// ldmatrix x4 (non-trans)
__device__ __forceinline__ void ldsm4(uint32_t r[4], uint32_t addr) {
    asm volatile("ldmatrix.sync.aligned.m8n8.x4.shared.b16 {%0,%1,%2,%3}, [%4];"
                 : "=r"(r[0]), "=r"(r[1]), "=r"(r[2]), "=r"(r[3]) : "r"(addr));
}
// mma m16n8k16 row.col bf16 -> f32
__device__ __forceinline__ void mma16816(float c[4], const uint32_t a[4],
                                         uint32_t b0, uint32_t b1) {
    asm volatile("mma.sync.aligned.m16n8k16.row.col.f32.bf16.bf16.f32 "
                 "{%0,%1,%2,%3},{%4,%5,%6,%7},{%8,%9},{%0,%1,%2,%3};"
                 : "+f"(c[0]), "+f"(c[1]), "+f"(c[2]), "+f"(c[3])
                 : "r"(a[0]), "r"(a[1]), "r"(a[2]), "r"(a[3]), "r"(b0), "r"(b1));
}

// ================= Kernel 1: x[b,f,n,m] -> H[b][m][0..31][n] =================
__global__ __launch_bounds__(256) void k_transpose(const float* __restrict__ x) {
    int id = blockIdx.x;           // ((b*32 + f)*8 + nt)
    int nt = id & 7;
    int f  = (id >> 3) & 31;
    int b  = id >> 8;

    __shared__ float ts[32][65];
    int t  = threadIdx.x;
    int m  = t & 63;
    int nl = t >> 6;               // 0..3
    const float* xp = x + ((size_t)(b * F_IN + f) * CN + nt * 32) * M_;
#pragma unroll
    for (int i = 0; i < 8; ++i) {
        int r = nl + 4 * i;
        ts[r][m] = xp[(size_t)r * M_ + m];
    }
    __syncthreads();
    int nl2 = t & 31;
    int mg  = t >> 5;              // 0..7
#pragma unroll
    for (int i = 0; i < 8; ++i) {
        int mm = mg + 8 * i;
        g_H[((size_t)(b * M_ + mm) * C_CAT + f) * CN + nt * 32 + nl2] = ts[nl2][mm];
    }
}

// ================= Kernel 2: HMMA fused double-hop nconv =================
// One CTA per (base, b, m). D[v(256) x f(32)] = sum_n A[n][v] * x[f][n]
// mma.sync m16n8k16 bf16, fp32 accum, 3-term hi/lo split.
//
// smem layout (b32 strides): xs[f=32][np=128] stride 132; As[v=256][np=16] stride 20
// (rows must be 16B aligned for ldmatrix: 20*4 = 80 B, multiple of 16).
#define AS_STR 20
#define XS_STR 132
#define SM_XS_HI 0u
#define SM_XS_LO 16896u
#define SM_AS_HI 33792u          // 256*20*4 = 20480 B
#define SM_AS_LO 54272u          // + 20480
#define SM_X1    33792u          // fp32 [256][33] (33792 B), aliases As region
#define SM_TOT   74752u

__global__ __launch_bounds__(256, 2) void k_nconv(const float* __restrict__ b0,
                                                  const float* __restrict__ b1,
                                                  const float* __restrict__ b2)
{
    extern __shared__ char smem[];
    uint32_t sb = smem_u32(smem);
    int t   = threadIdx.x;
    int wid = t >> 5;
    int l   = t & 31;

    int id = blockIdx.x;                    // 0..1535
    int kb = id >> 9;
    int bm = id & 511;
    const float* Ag = (kb == 0 ? b0 : (kb == 1 ? b1 : b2)) + (size_t)bm * (CN * CN);
    float* Hbm = g_H + (size_t)bm * (C_CAT * CN);

    // ---- prefetch A chunk 0 (32 n-rows) into registers ----
    float pf[32];
#pragma unroll
    for (int i = 0; i < 32; ++i)
        pf[i] = __ldg(Ag + (size_t)i * CN + t);

    // ---- build xs (hi/lo) from piece 0 [f][n] fp32 ----
    {
        const float2* src = (const float2*)Hbm;
#pragma unroll
        for (int k = 0; k < 16; ++k) {
            int pos = t + 256 * k;          // f = pos>>7, np = pos&127
            int f = pos >> 7, np = pos & 127;
            float2 a = src[pos];
            uint32_t hi2, lo2; split2(a.x, a.y, hi2, lo2);
            uint32_t off = (uint32_t)(f * XS_STR + np) * 4u;
            *(uint32_t*)(smem + SM_XS_HI + off) = hi2;
            *(uint32_t*)(smem + SM_XS_LO + off) = lo2;
        }
    }

    // ---- per-lane ldmatrix base addresses ----
    int sub  = l >> 3;                      // 0..3
    int arow = (l & 7) + 8 * (sub & 1);
    int anp  = 4 * (sub >> 1);
    uint32_t aA  = sb + SM_AS_HI + (uint32_t)((32 * wid + arow) * AS_STR + anp) * 4u;
    uint32_t aX0 = sb + SM_XS_HI + (uint32_t)(arow * XS_STR + anp) * 4u;
    uint32_t aX1 = sb + SM_XS_HI + (uint32_t)((16 + arow) * XS_STR + anp) * 4u;
    const uint32_t ALO = SM_AS_LO - SM_AS_HI;   // 20480
    const uint32_t XLO = SM_XS_LO - SM_XS_HI;   // 16896

    int grp = l >> 2, qp = l & 3;

    __syncthreads();

    for (int h = 0; h < 2; ++h) {
        float acc[2][4][4];
#pragma unroll
        for (int mt = 0; mt < 2; ++mt)
#pragma unroll
            for (int nt = 0; nt < 4; ++nt)
#pragma unroll
                for (int e = 0; e < 4; ++e) acc[mt][nt][e] = 0.0f;

        for (int c = 0; c < 8; ++c) {
            // convert prefetched chunk -> As hi/lo (v = t, 16 n-pairs)
#pragma unroll
            for (int j = 0; j < 16; ++j) {
                uint32_t hi2, lo2; split2(pf[2 * j], pf[2 * j + 1], hi2, lo2);
                uint32_t off = (uint32_t)(t * AS_STR + j) * 4u;
                *(uint32_t*)(smem + SM_AS_HI + off) = hi2;
                *(uint32_t*)(smem + SM_AS_LO + off) = lo2;
            }
            __syncthreads();

            // prefetch next chunk (overlaps with MMA below)
            if (c < 7) {
                const float* src = Ag + (size_t)(c + 1) * 32 * CN + t;
#pragma unroll
                for (int i = 0; i < 32; ++i) pf[i] = __ldg(src + (size_t)i * CN);
            } else if (h == 0) {
                const float* src = Ag + t;      // hop-2 chunk 0 (L2 hit)
#pragma unroll
                for (int i = 0; i < 32; ++i) pf[i] = __ldg(src + (size_t)i * CN);
            }

            // MMA: 2 k-steps of 16
#pragma unroll
            for (int ks = 0; ks < 2; ++ks) {
                uint32_t npl = 8u * ks;             // local A offset (b32)
                uint32_t npg = 16u * c + 8u * ks;   // global x offset (b32)
                uint32_t aH[2][4], aL[2][4], xH[2][4], xL[2][4];
                ldsm4(aH[0], aA + npl * 4u);
                ldsm4(aH[1], aA + (16u * AS_STR + npl) * 4u);
                ldsm4(aL[0], aA + ALO + npl * 4u);
                ldsm4(aL[1], aA + ALO + (16u * AS_STR + npl) * 4u);
                ldsm4(xH[0], aX0 + npg * 4u);
                ldsm4(xH[1], aX1 + npg * 4u);
                ldsm4(xL[0], aX0 + XLO + npg * 4u);
                ldsm4(xL[1], aX1 + XLO + npg * 4u);
#pragma unroll
                for (int mt = 0; mt < 2; ++mt)
#pragma unroll
                    for (int fb = 0; fb < 2; ++fb) {
                        mma16816(acc[mt][2 * fb],     aH[mt], xH[fb][0], xH[fb][2]);
                        mma16816(acc[mt][2 * fb + 1], aH[mt], xH[fb][1], xH[fb][3]);
                        mma16816(acc[mt][2 * fb],     aL[mt], xH[fb][0], xH[fb][2]);
                        mma16816(acc[mt][2 * fb + 1], aL[mt], xH[fb][1], xH[fb][3]);
                        mma16816(acc[mt][2 * fb],     aH[mt], xL[fb][0], xL[fb][2]);
                        mma16816(acc[mt][2 * fb + 1], aH[mt], xL[fb][1], xL[fb][3]);
                    }
            }
            __syncthreads();
        }

        // ---- epilogue: write piece to global; (h==0) rebuild xs from result ----
        int piece = 1 + 2 * kb + h;
        float* Hp = Hbm + (size_t)(32 * piece) * CN;
#pragma unroll
        for (int mt = 0; mt < 2; ++mt)
#pragma unroll
            for (int nt = 0; nt < 4; ++nt) {
                int v0 = 32 * wid + 16 * mt + grp;
                int f0 = 8 * nt + 2 * qp;
                Hp[(size_t)f0 * CN + v0]           = acc[mt][nt][0];
                Hp[(size_t)(f0 + 1) * CN + v0]     = acc[mt][nt][1];
                Hp[(size_t)f0 * CN + v0 + 8]       = acc[mt][nt][2];
                Hp[(size_t)(f0 + 1) * CN + v0 + 8] = acc[mt][nt][3];
            }

        if (h == 0) {
            float* x1s = (float*)(smem + SM_X1);    // aliases As (idle now)
            __syncthreads();                         // all MMAs done reading As
#pragma unroll
            for (int mt = 0; mt < 2; ++mt)
#pragma unroll
                for (int nt = 0; nt < 4; ++nt) {
                    int v0 = 32 * wid + 16 * mt + grp;
                    int f0 = 8 * nt + 2 * qp;
                    x1s[v0 * 33 + f0]           = acc[mt][nt][0];
                    x1s[v0 * 33 + f0 + 1]       = acc[mt][nt][1];
                    x1s[(v0 + 8) * 33 + f0]     = acc[mt][nt][2];
                    x1s[(v0 + 8) * 33 + f0 + 1] = acc[mt][nt][3];
                }
            __syncthreads();
            // xs[f][n=v] <- x1s[v][f]
            int f = t & 31, g8 = t >> 5;
#pragma unroll
            for (int k = 0; k < 16; ++k) {
                int np = g8 + 8 * k;
                float a0 = x1s[(2 * np) * 33 + f];
                float a1 = x1s[(2 * np + 1) * 33 + f];
                uint32_t hi2, lo2; split2(a0, a1, hi2, lo2);
                uint32_t off = (uint32_t)(f * XS_STR + np) * 4u;
                *(uint32_t*)(smem + SM_XS_HI + off) = hi2;
                *(uint32_t*)(smem + SM_XS_LO + off) = lo2;
            }
            __syncthreads();
        }
    }
}

// ================= Kernel 3: y[b,o,c,m] = W[o,:] . H[b][m][:][c] + bias[o] =================
__global__ __launch_bounds__(256, 2) void k_final(const float* __restrict__ W,
                                                  const float* __restrict__ bias,
                                                  float* __restrict__ y)
{
    extern __shared__ float smemf[];
    float* Ws = smemf;                      // 224*68 transposed W: Ws[fc][o]
    float* Hs = Ws + C_CAT * WS_STRIDE;     // 2*KC*256

    int bm = blockIdx.x;
    int b  = bm >> 6;
    int m  = bm & 63;
    const float* Hbm = g_H + (size_t)bm * (C_CAT * CN);

    int t  = threadIdx.x;
    int tv = t & 31;
    int og = t >> 5;                        // 0..7

    int lr = t >> 6;
    int lc = (t & 63) * 4;

#pragma unroll
    for (int r = 0; r < 4; ++r)
        cp_async16(smem_u32(&Hs[(lr + 4 * r) * CN + lc]), Hbm + (size_t)(lr + 4 * r) * CN + lc);
    cp_commit();

    for (int i = t; i < C_OUT * C_CAT; i += 256) {
        int o = i / C_CAT, fc = i % C_CAT;
        Ws[fc * WS_STRIDE + o] = W[i];
    }
    float bv[8];
#pragma unroll
    for (int i = 0; i < 8; ++i) bv[i] = bias[8 * og + i];

    uint64_t acc2[4][2][4];
#pragma unroll
    for (int p = 0; p < 4; ++p)
#pragma unroll
        for (int q = 0; q < 2; ++q)
#pragma unroll
            for (int j = 0; j < 4; ++j) acc2[p][q][j] = 0ull;

    const int NCH = C_CAT / KC;  // 14
    for (int ch = 0; ch < NCH; ++ch) {
        float* buf = Hs + (ch & 1) * (KC * CN);
        if (ch < NCH - 1) {
            float* nbuf = Hs + ((ch + 1) & 1) * (KC * CN);
            const float* Hc = Hbm + (size_t)(ch + 1) * KC * CN;
#pragma unroll
            for (int r = 0; r < 4; ++r)
                cp_async16(smem_u32(&nbuf[(lr + 4 * r) * CN + lc]), Hc + (size_t)(lr + 4 * r) * CN + lc);
            cp_commit();
            cp_wait<1>();
        } else {
            cp_wait<0>();
        }
        __syncthreads();
#pragma unroll
        for (int kk = 0; kk < KC; ++kk) {
            float4 w0 = *(const float4*)&Ws[(ch * KC + kk) * WS_STRIDE + 8 * og];
            float4 w1 = *(const float4*)&Ws[(ch * KC + kk) * WS_STRIDE + 8 * og + 4];
            float4 h0 = *(const float4*)&buf[kk * CN + 4 * tv];
            float4 h1 = *(const float4*)&buf[kk * CN + 128 + 4 * tv];
            uint64_t wp[4] = { pk2(w0.x, w0.y), pk2(w0.z, w0.w),
                               pk2(w1.x, w1.y), pk2(w1.z, w1.w) };
            uint64_t hd[2][4] = {
                { pk2(h0.x, h0.x), pk2(h0.y, h0.y), pk2(h0.z, h0.z), pk2(h0.w, h0.w) },
                { pk2(h1.x, h1.x), pk2(h1.y, h1.y), pk2(h1.z, h1.z), pk2(h1.w, h1.w) }
            };
#pragma unroll
            for (int p = 0; p < 4; ++p)
#pragma unroll
                for (int q = 0; q < 2; ++q)
#pragma unroll
                    for (int j = 0; j < 4; ++j)
                        ffma2(acc2[p][q][j], wp[p], hd[q][j]);
        }
        __syncthreads();
    }

#pragma unroll
    for (int p = 0; p < 4; ++p) {
#pragma unroll
        for (int q = 0; q < 2; ++q)
#pragma unroll
            for (int j = 0; j < 4; ++j) {
                float lo, hi;
                upk2(acc2[p][q][j], lo, hi);
                int o0 = 8 * og + 2 * p;
                int c  = 128 * q + 4 * tv + j;
                size_t ob0 = ((size_t)(b * C_OUT + o0) * CN + c) * M_ + m;
                size_t ob1 = ((size_t)(b * C_OUT + o0 + 1) * CN + c) * M_ + m;
                y[ob0] = lo + bv[2 * p];
                y[ob1] = hi + bv[2 * p + 1];
            }
    }
}

// ================= launch =================
extern "C" void kernel_launch(void* const* d_in, const int* in_sizes, int n_in,
                              void* d_out, int out_size) {
    const float* x    = (const float*)d_in[0];
    const float* b0   = (const float*)d_in[1];
    const float* b1   = (const float*)d_in[2];
    const float* b2   = (const float*)d_in[3];
    const float* W    = (const float*)d_in[4];
    const float* bias = (const float*)d_in[5];
    float* y = (float*)d_out;

    const int SMEM_K3 = (C_CAT * WS_STRIDE + 2 * KC * CN) * 4;     // 93,696 B
    cudaFuncSetAttribute(k_nconv, cudaFuncAttributeMaxDynamicSharedMemorySize, (int)SM_TOT);
    cudaFuncSetAttribute(k_final, cudaFuncAttributeMaxDynamicSharedMemorySize, SMEM_K3);

    k_transpose<<<2048, 256>>>(x);
    k_nconv<<<1536, 256, SM_TOT>>>(b0, b1, b2);
    k_final<<<512, 256, SMEM_K3>>>(W, bias, y);
}